// round 1
// baseline (speedup 1.0000x reference)
#include <cuda_runtime.h>

// EquiLocalPatOrientConvolution: B=2, I=32, O=64, D=H=W=48, K=5 (pad 2),
// filter = Y0 * sum_p W[o,i,p] * radial_mask_p  (masks partition the 125 taps).
// Fused: per-tile radial sums (10 classes) then channel-mixing GEMM.

#define DIMS   48
#define TILE   8
#define HALO   12            // TILE + 4
#define NI     32
#define NO     64
#define NP     10
#define Y0C    0.28209479177387814f
#define NTHR   256
#define NVOX   512           // TILE^3

// distinct r^2 values in 5^3 grid: 0,1,2,3,4,5,6,8,9,12 -> p index 0..9
__device__ __host__ constexpr int p_of_r2(int r2) {
    return r2 <= 6 ? r2 : (r2 == 8 ? 7 : (r2 == 9 ? 8 : 9));
}

// smem layout (floats): W[NI*NP*NO] | xs[HALO^3] | Ys[NP*NVOX]
#define WS_FLOATS  (NI * NP * NO)                  // 20480
#define XS_FLOATS  (HALO * HALO * HALO)            // 1728
#define YS_FLOATS  (NP * NVOX)                     // 5120
#define SMEM_FLOATS (WS_FLOATS + XS_FLOATS + YS_FLOATS)
#define SMEM_BYTES  (SMEM_FLOATS * 4)              // 109312

__global__ void __launch_bounds__(NTHR, 1)
econv_kernel(const float* __restrict__ x,
             const float* __restrict__ wg,
             const float* __restrict__ bias,
             float* __restrict__ out)
{
    extern __shared__ float smem[];
    float* Ws = smem;                       // [i][p][o]  (o contiguous)
    float* xs = smem + WS_FLOATS;           // [HALO][HALO][HALO]
    float* Ys = xs + XS_FLOATS;             // [p][NVOX]

    const int tid = threadIdx.x;
    const int b   = blockIdx.y;
    const int t   = blockIdx.x;
    const int tz  = t / 36;
    const int ty  = (t % 36) / 6;
    const int tx  = t % 6;
    const int z0  = tz * TILE, y0 = ty * TILE, x0 = tx * TILE;

    // ---- preload all W into smem, layout Ws[(i*NP+p)*NO + o] ----
    for (int idx = tid; idx < NO * NI * NP; idx += NTHR) {
        int o = idx / (NI * NP);
        int r = idx % (NI * NP);
        int i = r / NP;
        int p = r % NP;
        Ws[(i * NP + p) * NO + o] = wg[idx];
    }

    // GEMM thread tile: 8 outputs x 16 voxels
    const int og = tid & 7;          // o-group
    const int vg = tid >> 3;         // v-group (0..31)
    const int o0 = og * 8;
    const int v0 = vg * 16;

    float acc[128];
    #pragma unroll
    for (int k = 0; k < 128; k++) acc[k] = 0.0f;

    const size_t x_chan  = (size_t)DIMS * DIMS * DIMS;     // 110592
    const float* xb = x + (size_t)b * NI * x_chan;

    for (int ci = 0; ci < NI; ci++) {
        __syncthreads();   // previous iter's GEMM done before xs/Ys overwrite

        // ---- load 12^3 halo tile (zero-padded) ----
        const float* xc = xb + (size_t)ci * x_chan;
        for (int idx = tid; idx < XS_FLOATS; idx += NTHR) {
            int zz = idx / (HALO * HALO);
            int r  = idx % (HALO * HALO);
            int yy = r / HALO;
            int xx = r % HALO;
            int gz = z0 + zz - 2, gy = y0 + yy - 2, gx = x0 + xx - 2;
            float v = 0.0f;
            if ((unsigned)gz < (unsigned)DIMS &&
                (unsigned)gy < (unsigned)DIMS &&
                (unsigned)gx < (unsigned)DIMS)
                v = xc[(gz * DIMS + gy) * DIMS + gx];
            xs[idx] = v;
        }
        __syncthreads();

        // ---- build radial sums: 2 voxels per thread ----
        #pragma unroll
        for (int vv = 0; vv < 2; vv++) {
            int v  = tid + vv * NTHR;
            int vz = v >> 6;
            int vy = (v >> 3) & 7;
            int vx = v & 7;
            float yr[NP];
            #pragma unroll
            for (int p = 0; p < NP; p++) yr[p] = 0.0f;
            #pragma unroll
            for (int dz = 0; dz < 5; dz++) {
                #pragma unroll
                for (int dy = 0; dy < 5; dy++) {
                    const float* row = &xs[((vz + dz) * HALO + (vy + dy)) * HALO + vx];
                    #pragma unroll
                    for (int dx = 0; dx < 5; dx++) {
                        const int p = p_of_r2((dz - 2) * (dz - 2) +
                                              (dy - 2) * (dy - 2) +
                                              (dx - 2) * (dx - 2));
                        yr[p] += row[dx];
                    }
                }
            }
            #pragma unroll
            for (int p = 0; p < NP; p++) Ys[p * NVOX + v] = yr[p];
        }
        __syncthreads();

        // ---- channel-mix accumulate: acc[j][l] += W[o0+j][ci][p] * Y[p][v0+l] ----
        const float* wbase = &Ws[(ci * NP) * NO];
        #pragma unroll
        for (int p = 0; p < NP; p++) {
            const float4 w0 = *(const float4*)&wbase[p * NO + o0];
            const float4 w1 = *(const float4*)&wbase[p * NO + o0 + 4];
            const float* yrow = &Ys[p * NVOX + v0];
            const float4 ya = *(const float4*)&yrow[0];
            const float4 yb = *(const float4*)&yrow[4];
            const float4 yc = *(const float4*)&yrow[8];
            const float4 yd = *(const float4*)&yrow[12];
            float wv[8] = {w0.x, w0.y, w0.z, w0.w, w1.x, w1.y, w1.z, w1.w};
            float yv[16] = {ya.x, ya.y, ya.z, ya.w, yb.x, yb.y, yb.z, yb.w,
                            yc.x, yc.y, yc.z, yc.w, yd.x, yd.y, yd.z, yd.w};
            #pragma unroll
            for (int j = 0; j < 8; j++) {
                #pragma unroll
                for (int l = 0; l < 16; l++)
                    acc[j * 16 + l] += wv[j] * yv[l];
            }
        }
    }

    // ---- epilogue: scale by Y0, add bias, vectorized stores ----
    #pragma unroll
    for (int j = 0; j < 8; j++) {
        const float bb = __ldg(&bias[o0 + j]);
        float* obase = out + ((size_t)(b * NO + o0 + j)) * x_chan;
        #pragma unroll
        for (int half = 0; half < 2; half++) {
            int v  = v0 + half * 8;
            int gz = z0 + (v >> 6);
            int gy = y0 + ((v >> 3) & 7);
            int gx = x0;
            float4 r0, r1;
            r0.x = Y0C * acc[j * 16 + half * 8 + 0] + bb;
            r0.y = Y0C * acc[j * 16 + half * 8 + 1] + bb;
            r0.z = Y0C * acc[j * 16 + half * 8 + 2] + bb;
            r0.w = Y0C * acc[j * 16 + half * 8 + 3] + bb;
            r1.x = Y0C * acc[j * 16 + half * 8 + 4] + bb;
            r1.y = Y0C * acc[j * 16 + half * 8 + 5] + bb;
            r1.z = Y0C * acc[j * 16 + half * 8 + 6] + bb;
            r1.w = Y0C * acc[j * 16 + half * 8 + 7] + bb;
            float* dst = &obase[(gz * DIMS + gy) * DIMS + gx];
            *(float4*)&dst[0] = r0;
            *(float4*)&dst[4] = r1;
        }
    }
}

extern "C" void kernel_launch(void* const* d_in, const int* in_sizes, int n_in,
                              void* d_out, int out_size)
{
    const float* x    = (const float*)d_in[0];   // [2,32,1,48,48,48]
    const float* w    = (const float*)d_in[1];   // [64,32,1,1,1,10]
    const float* bias = (const float*)d_in[2];   // [64]
    // d_in[3] = masks (structure baked in via p_of_r2)
    float* out = (float*)d_out;                  // [2,64,1,48,48,48]

    cudaFuncSetAttribute(econv_kernel,
                         cudaFuncAttributeMaxDynamicSharedMemorySize, SMEM_BYTES);
    dim3 grid(216, 2);   // 6^3 spatial tiles x batch
    econv_kernel<<<grid, NTHR, SMEM_BYTES>>>(x, w, bias, out);
}

// round 2
// speedup vs baseline: 1.2548x; 1.2548x over previous
#include <cuda_runtime.h>

// EquiLocalPatOrientConvolution: B=2, I=32, O=64, D=H=W=48, K=5 (pad 2).
// filter = Y0 * sum_p W[o,i,p] * radial_mask_p (masks partition the 125 taps).
// Fused per-tile: radial sums (10 r^2 classes) -> channel-mix GEMM (f32x2 FMA).

#define DIMS   48
#define TILE   8
#define HALO   12
#define NI     32
#define NO     64
#define NP     10
#define Y0C    0.28209479177387814f
#define NTHR   512
#define NVOX   512

__device__ __host__ constexpr int p_of_r2(int r2) {
    return r2 <= 6 ? r2 : (r2 == 8 ? 7 : (r2 == 9 ? 8 : 9));
}

#define WS_FLOATS  (NI * NP * NO)        // 20480
#define XS_FLOATS  (HALO * HALO * HALO)  // 1728
#define YS_FLOATS  (NP * NVOX)           // 5120
#define SMEM_BYTES ((WS_FLOATS + 2 * XS_FLOATS + YS_FLOATS) * 4)  // 116224

__device__ __forceinline__ float2 ffma2(float2 a, float2 b, float2 c) {
    unsigned long long ua = *reinterpret_cast<unsigned long long*>(&a);
    unsigned long long ub = *reinterpret_cast<unsigned long long*>(&b);
    unsigned long long uc = *reinterpret_cast<unsigned long long*>(&c);
    unsigned long long ud;
    asm("fma.rn.f32x2 %0, %1, %2, %3;" : "=l"(ud) : "l"(ua), "l"(ub), "l"(uc));
    return *reinterpret_cast<float2*>(&ud);
}

__global__ void __launch_bounds__(NTHR, 1)
econv_kernel(const float* __restrict__ x,
             const float* __restrict__ wg,
             const float* __restrict__ bias,
             float* __restrict__ out)
{
    extern __shared__ float smem[];
    float* Ws  = smem;                       // [i][p][o] (o contiguous)
    float* xsA = smem + WS_FLOATS;           // halo buffer 0
    float* xsB = xsA + XS_FLOATS;            // halo buffer 1
    float* Ys  = xsB + XS_FLOATS;            // [p][NVOX]

    const int tid = threadIdx.x;
    const int b   = blockIdx.y;
    const int t   = blockIdx.x;
    const int tz  = t / 36;
    const int ty  = (t % 36) / 6;
    const int tx  = t % 6;
    const int z0  = tz * TILE, y0 = ty * TILE, x0 = tx * TILE;

    // ---- preload all W into smem: Ws[(i*NP+p)*NO + o] = wg[o][i][p] ----
    for (int idx = tid; idx < WS_FLOATS; idx += NTHR) {
        int o = idx / (NI * NP);
        int r = idx % (NI * NP);
        Ws[r * NO + o] = wg[idx];
    }

    const size_t x_chan = (size_t)DIMS * DIMS * DIMS;   // 110592
    const float* xb = x + (size_t)b * NI * x_chan;

    // GEMM thread tile: 8 outputs x 8 voxels
    const int og = tid & 7;
    const int vg = tid >> 3;        // 0..63
    const int o0 = og * 8;
    const int v0 = vg * 8;

    float2 acc[32];
    #pragma unroll
    for (int k = 0; k < 32; k++) acc[k] = make_float2(0.f, 0.f);

    // halo-tile prefetch (gmem -> regs), 4 elems per thread
    float pre[4];
    auto do_prefetch = [&](int ci) {
        const float* xc = xb + (size_t)ci * x_chan;
        #pragma unroll
        for (int k = 0; k < 4; k++) {
            int idx = tid + k * NTHR;
            float v = 0.0f;
            if (idx < XS_FLOATS) {
                int zz = idx / (HALO * HALO);
                int rr = idx % (HALO * HALO);
                int yy = rr / HALO, xx = rr % HALO;
                int gz = z0 + zz - 2, gy = y0 + yy - 2, gx = x0 + xx - 2;
                if ((unsigned)gz < (unsigned)DIMS &&
                    (unsigned)gy < (unsigned)DIMS &&
                    (unsigned)gx < (unsigned)DIMS)
                    v = __ldg(&xc[(gz * DIMS + gy) * DIMS + gx]);
            }
            pre[k] = v;
        }
    };
    auto commit = [&](float* dst) {
        #pragma unroll
        for (int k = 0; k < 4; k++) {
            int idx = tid + k * NTHR;
            if (idx < XS_FLOATS) dst[idx] = pre[k];
        }
    };
    // radial sums: 1 voxel per thread, 125 taps -> 10 classes
    auto radial = [&](const float* xsb) {
        const int vz = tid >> 6, vy = (tid >> 3) & 7, vx = tid & 7;
        float yr[NP];
        #pragma unroll
        for (int p = 0; p < NP; p++) yr[p] = 0.0f;
        #pragma unroll
        for (int dz = 0; dz < 5; dz++) {
            #pragma unroll
            for (int dy = 0; dy < 5; dy++) {
                const float* row = &xsb[((vz + dz) * HALO + (vy + dy)) * HALO + vx];
                #pragma unroll
                for (int dx = 0; dx < 5; dx++) {
                    const int p = p_of_r2((dz - 2) * (dz - 2) +
                                          (dy - 2) * (dy - 2) +
                                          (dx - 2) * (dx - 2));
                    yr[p] += row[dx];
                }
            }
        }
        #pragma unroll
        for (int p = 0; p < NP; p++) Ys[p * NVOX + tid] = yr[p];
    };

    // ---- prologue: halo + radial for ci = 0 ----
    do_prefetch(0);
    commit(xsA);
    __syncthreads();
    radial(xsA);

    float* xsbuf[2] = { xsA, xsB };
    int buf = 0;

    for (int ci = 0; ci < NI; ci++) {
        if (ci + 1 < NI) do_prefetch(ci + 1);   // LDGs hidden behind GEMM
        __syncthreads();                        // Ys(ci) ready

        // ---- channel-mix: acc[j][l] += W[o0+j][ci][p] * Y[p][v0..v0+7] ----
        const float* wbase = &Ws[(ci * NP) * NO];
        #pragma unroll
        for (int p = 0; p < NP; p++) {
            const float4 w0 = *(const float4*)&wbase[p * NO + o0];
            const float4 w1 = *(const float4*)&wbase[p * NO + o0 + 4];
            const float* yrow = &Ys[p * NVOX + v0];
            const float4 ya = *(const float4*)&yrow[0];
            const float4 yb = *(const float4*)&yrow[4];
            float  wv[8] = { w0.x, w0.y, w0.z, w0.w, w1.x, w1.y, w1.z, w1.w };
            float2 yv[4] = { {ya.x, ya.y}, {ya.z, ya.w}, {yb.x, yb.y}, {yb.z, yb.w} };
            #pragma unroll
            for (int j = 0; j < 8; j++) {
                float2 wj = make_float2(wv[j], wv[j]);
                #pragma unroll
                for (int l = 0; l < 4; l++)
                    acc[j * 4 + l] = ffma2(wj, yv[l], acc[j * 4 + l]);
            }
        }

        if (ci + 1 < NI) {
            commit(xsbuf[buf ^ 1]);
            __syncthreads();          // xs(ci+1) visible; GEMM(ci) done with Ys
            radial(xsbuf[buf ^ 1]);   // build Ys(ci+1)
            buf ^= 1;
        }
    }

    // ---- epilogue: out = Y0*acc + bias ----
    const int vz = vg >> 3, vy = vg & 7;
    const float2 scl = make_float2(Y0C, Y0C);
    #pragma unroll
    for (int j = 0; j < 8; j++) {
        const float bb = __ldg(&bias[o0 + j]);
        const float2 bp = make_float2(bb, bb);
        float* dst = out + ((size_t)(b * NO + o0 + j)) * x_chan
                         + ((size_t)(z0 + vz) * DIMS + (y0 + vy)) * DIMS + x0;
        float2 r0 = ffma2(acc[j * 4 + 0], scl, bp);
        float2 r1 = ffma2(acc[j * 4 + 1], scl, bp);
        float2 r2 = ffma2(acc[j * 4 + 2], scl, bp);
        float2 r3 = ffma2(acc[j * 4 + 3], scl, bp);
        float4 s0 = make_float4(r0.x, r0.y, r1.x, r1.y);
        float4 s1 = make_float4(r2.x, r2.y, r3.x, r3.y);
        *(float4*)&dst[0] = s0;
        *(float4*)&dst[4] = s1;
    }
}

extern "C" void kernel_launch(void* const* d_in, const int* in_sizes, int n_in,
                              void* d_out, int out_size)
{
    const float* x    = (const float*)d_in[0];   // [2,32,1,48,48,48]
    const float* w    = (const float*)d_in[1];   // [64,32,1,1,1,10]
    const float* bias = (const float*)d_in[2];   // [64]
    float* out = (float*)d_out;                  // [2,64,1,48,48,48]

    cudaFuncSetAttribute(econv_kernel,
                         cudaFuncAttributeMaxDynamicSharedMemorySize, SMEM_BYTES);
    dim3 grid(216, 2);
    econv_kernel<<<grid, NTHR, SMEM_BYTES>>>(x, w, bias, out);
}